// round 1
// baseline (speedup 1.0000x reference)
#include <cuda_runtime.h>

// Shapes (fixed by the problem)
#define B 4
#define H 64
#define W 64
#define BANDS 128
#define C 32
#define NPIX (B * H * W)          // 16384
#define PIX_ELEMS (BANDS * C)     // 4096 floats per pixel in x/out

// Scratch for conv intermediates + final gamma/beta ([B,H,W,C] each = 2 MB)
__device__ float g_s1[NPIX * C];   // branch-A intermediate (gamma path conv1)
__device__ float g_s2[NPIX * C];   // branch-B intermediate (beta path conv1)
__device__ float g_gamma[NPIX * C];
__device__ float g_beta[NPIX * C];

__device__ __forceinline__ float lrelu(float v) {
    return v > 0.0f ? v : 0.3f * v;
}

// Dual-branch 3x3 SAME conv + LeakyReLU.
// warp = pixel, lane = output channel (C == 32 == warpSize).
// inA/inB: [B,H,W,C]; wA/wB: HWIO [3,3,C,C]; bA/bB: [C]; outA/outB: [B,H,W,C]
__global__ __launch_bounds__(256) void conv2_kernel(
    const float* __restrict__ inA, const float* __restrict__ inB,
    const float* __restrict__ wA,  const float* __restrict__ bA,
    const float* __restrict__ wB,  const float* __restrict__ bB,
    float* __restrict__ outA, float* __restrict__ outB)
{
    int warp = blockIdx.x * (blockDim.x >> 5) + (threadIdx.x >> 5); // pixel idx
    int lane = threadIdx.x & 31;                                     // out channel
    if (warp >= NPIX) return;

    int b  = warp >> 12;          // / (H*W)
    int h  = (warp >> 6) & 63;
    int w_ = warp & 63;

    float accA = bA[lane];
    float accB = bB[lane];

    #pragma unroll
    for (int ky = 0; ky < 3; ky++) {
        int hh = h + ky - 1;
        if (hh < 0 || hh >= H) continue;
        #pragma unroll
        for (int kx = 0; kx < 3; kx++) {
            int ww = w_ + kx - 1;
            if (ww < 0 || ww >= W) continue;
            int ibase = (((b * H + hh) * W) + ww) * C;
            int wbase = (ky * 3 + kx) * C * C + lane;
            #pragma unroll 8
            for (int ci = 0; ci < C; ci++) {
                float pa = __ldg(&inA[ibase + ci]);     // broadcast across lanes
                float pb = __ldg(&inB[ibase + ci]);
                accA = fmaf(pa, __ldg(&wA[wbase + ci * C]), accA); // coalesced
                accB = fmaf(pb, __ldg(&wB[wbase + ci * C]), accB);
            }
        }
    }
    outA[warp * C + lane] = lrelu(accA);
    outB[warp * C + lane] = lrelu(accB);
}

// FiLM: out[p, band, c] = x[p, band, c] * gamma[p, c] + beta[p, c]
// One block per pixel p; 256 threads, 4 float4 iterations each (1024 float4 = 4096 floats).
// c4 = t & 7 is invariant under the +256 stride, so gamma/beta load once per thread.
__global__ __launch_bounds__(256) void film_kernel(
    const float* __restrict__ x,
    const float* __restrict__ gamma,
    const float* __restrict__ beta,
    float* __restrict__ out)
{
    int p = blockIdx.x;
    int t = threadIdx.x;

    const float4* xp = (const float4*)(x + (size_t)p * PIX_ELEMS);
    float4*       op = (float4*)(out + (size_t)p * PIX_ELEMS);

    int c4 = t & 7;  // C/4 = 8 float4 groups per band
    float4 g  = ((const float4*)(gamma + p * C))[c4];
    float4 be = ((const float4*)(beta  + p * C))[c4];

    #pragma unroll
    for (int i = 0; i < 4; i++) {
        int j = t + i * 256;
        float4 v = xp[j];
        v.x = fmaf(v.x, g.x, be.x);
        v.y = fmaf(v.y, g.y, be.y);
        v.z = fmaf(v.z, g.z, be.z);
        v.w = fmaf(v.w, g.w, be.w);
        op[j] = v;
    }
}

extern "C" void kernel_launch(void* const* d_in, const int* in_sizes, int n_in,
                              void* d_out, int out_size)
{
    const float* x   = (const float*)d_in[0];
    const float* psi = (const float*)d_in[1];
    const float* gw1 = (const float*)d_in[2];
    const float* gb1 = (const float*)d_in[3];
    const float* gw2 = (const float*)d_in[4];
    const float* gb2 = (const float*)d_in[5];
    const float* bw1 = (const float*)d_in[6];
    const float* bb1 = (const float*)d_in[7];
    const float* bw2 = (const float*)d_in[8];
    const float* bb2 = (const float*)d_in[9];
    float* out = (float*)d_out;

    float *s1, *s2, *gm, *bt;
    cudaGetSymbolAddress((void**)&s1, g_s1);
    cudaGetSymbolAddress((void**)&s2, g_s2);
    cudaGetSymbolAddress((void**)&gm, g_gamma);
    cudaGetSymbolAddress((void**)&bt, g_beta);

    // 8 warps (pixels) per block -> 2048 blocks cover 16384 pixels
    conv2_kernel<<<NPIX / 8, 256>>>(psi, psi, gw1, gb1, bw1, bb1, s1, s2);
    conv2_kernel<<<NPIX / 8, 256>>>(s1, s2, gw2, gb2, bw2, bb2, gm, bt);
    film_kernel<<<NPIX, 256>>>(x, gm, bt, out);
}

// round 4
// speedup vs baseline: 1.1592x; 1.1592x over previous
#include <cuda_runtime.h>

// Shapes (fixed by the problem)
#define B 4
#define H 64
#define W 64
#define BANDS 128
#define C 32
#define NPIX (B * H * W)          // 16384
#define PIX_ELEMS (BANDS * C)     // 4096 floats per pixel in x/out

// Scratch for conv intermediates + final gamma/beta ([B,H,W,C] each = 2 MB)
__device__ float g_s1[NPIX * C];
__device__ float g_s2[NPIX * C];
__device__ float g_gamma[NPIX * C];
__device__ float g_beta[NPIX * C];

__device__ __forceinline__ float lrelu(float v) {
    return v > 0.0f ? v : 0.3f * v;
}

__device__ __forceinline__ float sel4(const float4& v, int k) {
    // k is a compile-time constant in the fully-unrolled loop below.
    return (k == 0) ? v.x : (k == 1) ? v.y : (k == 2) ? v.z : v.w;
}

// Dual-branch 3x3 SAME conv + LeakyReLU, vectorized.
// Thread = (pixel, co-group of 4). Warp covers 4 pixels x 8 co-groups.
// Weight loads (float4, contiguous in co) dedup across the 4 pixels in a warp
// (one 128B wavefront per warp-level load).
// inA/inB: [B,H,W,C]; wA/wB: HWIO [3,3,C,C]; bA/bB: [C]
__global__ __launch_bounds__(256) void conv2_kernel(
    const float* __restrict__ inA, const float* __restrict__ inB,
    const float* __restrict__ wA,  const float* __restrict__ bA,
    const float* __restrict__ wB,  const float* __restrict__ bB,
    float* __restrict__ outA, float* __restrict__ outB)
{
    int tid = blockIdx.x * blockDim.x + threadIdx.x;
    int p  = tid >> 3;        // pixel index
    int cg = tid & 7;         // output-channel group (4 channels)
    if (p >= NPIX) return;

    int b  = p >> 12;
    int h  = (p >> 6) & 63;
    int w_ = p & 63;

    float4 accA = ((const float4*)bA)[cg];
    float4 accB = ((const float4*)bB)[cg];

    #pragma unroll
    for (int ky = 0; ky < 3; ky++) {
        int hh = h + ky - 1;
        if (hh < 0 || hh >= H) continue;
        #pragma unroll
        for (int kx = 0; kx < 3; kx++) {
            int ww = w_ + kx - 1;
            if (ww < 0 || ww >= W) continue;
            int ibase = (((b * H + hh) * W) + ww) * C;     // psi row (C floats)
            int wtap  = ((ky * 3 + kx) * C) * C;           // tap base in HWIO

            #pragma unroll
            for (int g = 0; g < 8; g++) {                  // 8 ci-groups of 4
                float4 pa = __ldg((const float4*)(inA + ibase + g * 4));
                float4 pb = __ldg((const float4*)(inB + ibase + g * 4));

                #pragma unroll
                for (int k = 0; k < 4; k++) {
                    int ci = g * 4 + k;
                    float4 wa = __ldg((const float4*)(wA + wtap + ci * C + cg * 4));
                    float4 wb = __ldg((const float4*)(wB + wtap + ci * C + cg * 4));
                    float fa = sel4(pa, k);
                    float fb = sel4(pb, k);
                    accA.x = fmaf(fa, wa.x, accA.x);
                    accA.y = fmaf(fa, wa.y, accA.y);
                    accA.z = fmaf(fa, wa.z, accA.z);
                    accA.w = fmaf(fa, wa.w, accA.w);
                    accB.x = fmaf(fb, wb.x, accB.x);
                    accB.y = fmaf(fb, wb.y, accB.y);
                    accB.z = fmaf(fb, wb.z, accB.z);
                    accB.w = fmaf(fb, wb.w, accB.w);
                }
            }
        }
    }

    accA.x = lrelu(accA.x); accA.y = lrelu(accA.y);
    accA.z = lrelu(accA.z); accA.w = lrelu(accA.w);
    accB.x = lrelu(accB.x); accB.y = lrelu(accB.y);
    accB.z = lrelu(accB.z); accB.w = lrelu(accB.w);

    ((float4*)(outA + p * C))[cg] = accA;
    ((float4*)(outB + p * C))[cg] = accB;
}

// FiLM: out[p, band, c] = x[p, band, c] * gamma[p, c] + beta[p, c]
// One block per pixel; gamma/beta float4 loaded once per thread (c4 invariant
// under the +256 stride since C/4 = 8 divides 256).
__global__ __launch_bounds__(256) void film_kernel(
    const float* __restrict__ x,
    const float* __restrict__ gamma,
    const float* __restrict__ beta,
    float* __restrict__ out)
{
    int p = blockIdx.x;
    int t = threadIdx.x;

    const float4* xp = (const float4*)(x + (size_t)p * PIX_ELEMS);
    float4*       op = (float4*)(out + (size_t)p * PIX_ELEMS);

    int c4 = t & 7;
    float4 g  = ((const float4*)(gamma + p * C))[c4];
    float4 be = ((const float4*)(beta  + p * C))[c4];

    #pragma unroll
    for (int i = 0; i < 4; i++) {
        int j = t + i * 256;
        float4 v = xp[j];
        v.x = fmaf(v.x, g.x, be.x);
        v.y = fmaf(v.y, g.y, be.y);
        v.z = fmaf(v.z, g.z, be.z);
        v.w = fmaf(v.w, g.w, be.w);
        op[j] = v;
    }
}

extern "C" void kernel_launch(void* const* d_in, const int* in_sizes, int n_in,
                              void* d_out, int out_size)
{
    const float* x   = (const float*)d_in[0];
    const float* psi = (const float*)d_in[1];
    const float* gw1 = (const float*)d_in[2];
    const float* gb1 = (const float*)d_in[3];
    const float* gw2 = (const float*)d_in[4];
    const float* gb2 = (const float*)d_in[5];
    const float* bw1 = (const float*)d_in[6];
    const float* bb1 = (const float*)d_in[7];
    const float* bw2 = (const float*)d_in[8];
    const float* bb2 = (const float*)d_in[9];
    float* out = (float*)d_out;

    float *s1, *s2, *gm, *bt;
    cudaGetSymbolAddress((void**)&s1, g_s1);
    cudaGetSymbolAddress((void**)&s2, g_s2);
    cudaGetSymbolAddress((void**)&gm, g_gamma);
    cudaGetSymbolAddress((void**)&bt, g_beta);

    // NPIX*8 threads, 256/block -> 512 blocks
    conv2_kernel<<<NPIX * 8 / 256, 256>>>(psi, psi, gw1, gb1, bw1, bb1, s1, s2);
    conv2_kernel<<<NPIX * 8 / 256, 256>>>(s1, s2, gw2, gb2, bw2, bb2, gm, bt);
    film_kernel<<<NPIX, 256>>>(x, gm, bt, out);
}